// round 3
// baseline (speedup 1.0000x reference)
#include <cuda_runtime.h>
#include <math.h>
#include <stdint.h>

#define BATCH 64
#define H 64
#define W 96
#define HW (H * W)
#define UV 81
#define NCH 16

#define BX 64       // pixels per block
#define BY 3        // displacement chunks per pixel
#define CHUNK 27    // 81 / 3

// 1/ln(49), 1/ln(81)
#define INV_LN49 0.25694882f
#define INV_LN81 0.22756237f

// ---- packed f32x2 helpers ----
__device__ __forceinline__ uint64_t pk2(float a, float b) {
    uint64_t r;
    asm("mov.b64 %0, {%1, %2};" : "=l"(r) : "f"(a), "f"(b));
    return r;
}
__device__ __forceinline__ void upk2(uint64_t p, uint32_t& lo, uint32_t& hi) {
    asm("mov.b64 {%0, %1}, %2;" : "=r"(lo), "=r"(hi) : "l"(p));
}
#define FMA2(d, a, b, c) asm("fma.rn.f32x2 %0, %1, %2, %3;" : "=l"(d) : "l"(a), "l"(b), "l"(c))
#define MUL2(d, a, b)    asm("mul.rn.f32x2 %0, %1, %2;"     : "=l"(d) : "l"(a), "l"(b))
#define ADD2(d, a, b)    asm("add.rn.f32x2 %0, %1, %2;"     : "=l"(d) : "l"(a), "l"(b))

struct ExpConsts {
    uint64_t invln2, C, nC, nln2, c2, c3, c4, one;
};

// exp(d0), exp(d1) for d in [-87, 0] via FMA-pipe packed math (no MUFU).
// n = round(d/ln2); f = d - n*ln2; e^f = 1+f+f^2/2+f^3/6+f^4/24 (err ~4e-5);
// scale by 2^n folded into the float bit pattern (one ISCADD per half).
__device__ __forceinline__ void exp_pair(const ExpConsts& K, float d0, float d1,
                                         float& e0, float& e1) {
    uint64_t dp = pk2(d0, d1);
    uint64_t t, k, r, f, p;
    MUL2(t, dp, K.invln2);        // t = d / ln2
    ADD2(k, t, K.C);              // k = t + 1.5*2^23  (round-to-nearest in mantissa)
    ADD2(r, k, K.nC);             // r = round(t) = n  (as float)
    FMA2(f, r, K.nln2, dp);       // f = d - n*ln2,  f in [-0.347, 0.347]
    FMA2(p, f, K.c4, K.c3);       // Horner: (((f/24 + 1/6)f + 1/2)f + 1)f + 1
    FMA2(p, p, f, K.c2);
    FMA2(p, p, f, K.one);
    FMA2(p, p, f, K.one);
    uint32_t k0, k1, p0, p1;
    upk2(k, k0, k1);
    upk2(p, p0, p1);
    // bits(k) = bits(C) + n; (bits(C)<<23) == 0 mod 2^32, so (bits(k)<<23) == n<<23
    e0 = __int_as_float((int)(p0 + (k0 << 23)));
    e1 = __int_as_float((int)(p1 + (k1 << 23)));
}

__global__ __launch_bounds__(BX * BY) void segnet_flowreg_warp_kernel(
    const float* __restrict__ cost,
    const float* __restrict__ feat,
    float* __restrict__ out)
{
    __shared__ float s_max[BY][BX];
    __shared__ int   s_am [BY][BX];
    __shared__ float s_part[6][BY][BX];

    const int tx  = threadIdx.x;
    const int ty  = threadIdx.y;
    const int pix = blockIdx.x * BX + tx;      // b*HW + h*W + w
    const int b   = pix / HW;
    const int hw  = pix - b * HW;
    const int h   = hw / W;
    const int w   = hw - h * W;

    // ---- each ty loads its 27 cost slices (coalesced across tx) ----
    const float* cp = cost + (size_t)b * UV * HW + hw;
    float c[CHUNK];
    float m = -INFINITY;
    int   am = ty * CHUNK;
#pragma unroll
    for (int j = 0; j < CHUNK; j++) {
        float v = __ldg(cp + (size_t)(ty * CHUNK + j) * HW);
        c[j] = v;
        if (v > m) { m = v; am = ty * CHUNK + j; }  // strict > : first occurrence
    }
    s_max[ty][tx] = m;
    s_am [ty][tx] = am;
    __syncthreads();

    // ---- global max/argmax over the 3 chunks ----
    float gm  = s_max[0][tx];
    int   gam = s_am [0][tx];
#pragma unroll
    for (int t = 1; t < BY; t++) {
        float v = s_max[t][tx];
        if (v > gm) { gm = v; gam = s_am[t][tx]; }
    }
    const int u0 = gam / 9;
    const int v0 = gam - 9 * u0;

    // ---- packed-exp constants (register-resident pairs) ----
    ExpConsts K;
    K.invln2 = pk2(1.4426950408889634f, 1.4426950408889634f);
    K.C      = pk2(12582912.0f, 12582912.0f);
    K.nC     = pk2(-12582912.0f, -12582912.0f);
    K.nln2   = pk2(-0.6931471805599453f, -0.6931471805599453f);
    K.c2     = pk2(0.5f, 0.5f);
    K.c3     = pk2(0.16666666666f, 0.16666666666f);
    K.c4     = pk2(0.04166666666f, 0.04166666666f);
    K.one    = pk2(1.0f, 1.0f);

    // ---- partial exp sums; window max == global max (argmax in-window) ----
    // Per 9-row: v=0..3 through packed FMA-pipe exp (2 pairs), v=4..8 through MUFU.
    float Sg = 0.f, Sg1 = 0.f;      // global: sum e, sum e*d
    float Sw = 0.f, Sw1 = 0.f;      // 7x7 window sums
    float Sx = 0.f, Sy = 0.f;       // window displacement moments
#pragma unroll
    for (int ul = 0; ul < 3; ul++) {
        const int u = ty * 3 + ul;
        const bool uin = (u - u0 <= 3) && (u0 - u <= 3);
        float e[9], d[9];
#pragma unroll
        for (int v = 0; v < 9; v++) d[v] = c[ul * 9 + v] - gm;
        exp_pair(K, d[0], d[1], e[0], e[1]);
        exp_pair(K, d[2], d[3], e[2], e[3]);
#pragma unroll
        for (int v = 4; v < 9; v++) e[v] = __expf(d[v]);
#pragma unroll
        for (int v = 0; v < 9; v++) {
            Sg  += e[v];
            Sg1 += e[v] * d[v];
            bool inw = uin && (v - v0 <= 3) && (v0 - v <= 3);
            if (inw) {
                Sw  += e[v];
                Sw1 += e[v] * d[v];
                Sx  += e[v] * (float)(u - 4);
                Sy  += e[v] * (float)(v - 4);
            }
        }
    }
    s_part[0][ty][tx] = Sg;  s_part[1][ty][tx] = Sg1;
    s_part[2][ty][tx] = Sw;  s_part[3][ty][tx] = Sw1;
    s_part[4][ty][tx] = Sx;  s_part[5][ty][tx] = Sy;
    __syncthreads();

    // ---- every thread combines (redundant, sync-free) ----
    Sg = 0.f; Sg1 = 0.f; Sw = 0.f; Sw1 = 0.f; Sx = 0.f; Sy = 0.f;
#pragma unroll
    for (int t = 0; t < BY; t++) {
        Sg  += s_part[0][t][tx];  Sg1 += s_part[1][t][tx];
        Sw  += s_part[2][t][tx];  Sw1 += s_part[3][t][tx];
        Sx  += s_part[4][t][tx];  Sy  += s_part[5][t][tx];
    }
    const float invSw = 1.0f / Sw;
    const float fx = Sx * invSw;                             // flow x
    const float fy = Sy * invSw;                             // flow y

    float* flow_o = out;
    float* ent_o  = out + (size_t)BATCH * 2 * HW;
    float* warp_o = out + (size_t)BATCH * 4 * HW;

    if (ty == 0) {
        const float lent = (__logf(Sw) - Sw1 * invSw) * INV_LN49;
        const float gent = (__logf(Sg) - Sg1 / Sg)    * INV_LN81;
        flow_o[((size_t)b * 2 + 0) * HW + hw] = fx;
        flow_o[((size_t)b * 2 + 1) * HW + hw] = fy;
        ent_o [((size_t)b * 2 + 0) * HW + hw] = lent;
        ent_o [((size_t)b * 2 + 1) * HW + hw] = gent;
    }

    // ---- bilinear backward warp (align_corners=True, zero pad); channels over ty ----
    const float px = (float)w + fx;
    const float py = (float)h + fy;
    const float x0f = floorf(px), y0f = floorf(py);
    const float wx = px - x0f,   wy = py - y0f;
    const int x0 = (int)x0f, y0 = (int)y0f;
    const int x1 = x0 + 1,   y1 = y0 + 1;
    const bool vx0 = (x0 >= 0) & (x0 < W);
    const bool vx1 = (x1 >= 0) & (x1 < W);
    const bool vy0 = (y0 >= 0) & (y0 < H);
    const bool vy1 = (y1 >= 0) & (y1 < H);

    float w00 = (1.f - wx) * (1.f - wy) * ((vx0 & vy0) ? 1.f : 0.f);
    float w01 = wx         * (1.f - wy) * ((vx1 & vy0) ? 1.f : 0.f);
    float w10 = (1.f - wx) * wy         * ((vx0 & vy1) ? 1.f : 0.f);
    float w11 = wx         * wy         * ((vx1 & vy1) ? 1.f : 0.f);

    const float nx = 2.f * px / (float)(W - 1) - 1.f;
    const float ny = 2.f * py / (float)(H - 1) - 1.f;
    const float msk = (fabsf(nx) < 1.f && fabsf(ny) < 1.f) ? 1.f : 0.f;
    w00 *= msk; w01 *= msk; w10 *= msk; w11 *= msk;

    const int x0c = min(max(x0, 0), W - 1), x1c = min(max(x1, 0), W - 1);
    const int y0c = min(max(y0, 0), H - 1), y1c = min(max(y1, 0), H - 1);
    const int o00 = y0c * W + x0c, o01 = y0c * W + x1c;
    const int o10 = y1c * W + x0c, o11 = y1c * W + x1c;

    const float* fb = feat + (size_t)b * NCH * HW;
#pragma unroll
    for (int ch = ty; ch < NCH; ch += BY) {
        const float* f = fb + ch * HW;
        float val = w00 * __ldg(f + o00) + w01 * __ldg(f + o01)
                  + w10 * __ldg(f + o10) + w11 * __ldg(f + o11);
        warp_o[((size_t)b * NCH + ch) * HW + hw] = val;
    }
}

extern "C" void kernel_launch(void* const* d_in, const int* in_sizes, int n_in,
                              void* d_out, int out_size) {
    const float* cost = (const float*)d_in[0];
    const float* feat = (const float*)d_in[1];
    float* out = (float*)d_out;

    dim3 block(BX, BY);
    int blocks = (BATCH * HW) / BX;   // 6144
    segnet_flowreg_warp_kernel<<<blocks, block>>>(cost, feat, out);
}

// round 4
// speedup vs baseline: 1.0194x; 1.0194x over previous
#include <cuda_runtime.h>
#include <math.h>
#include <stdint.h>

#define BATCH 64
#define H 64
#define W 96
#define HW (H * W)
#define UV 81
#define NCH 16

#define TILE 64          // pixels per tile
#define BY 3             // displacement chunks per pixel
#define CHUNK 27         // 81 / 3
#define NTHREADS (TILE * BY)
#define G 4              // tiles per CTA
#define NTILES (BATCH * HW / TILE)        // 6144
#define NCHUNK16 (UV * TILE * 4 / 16)     // 1296 16B chunks per tile

#define INV_LN49 0.25694882f
#define INV_LN81 0.22756237f

__device__ __forceinline__ void cp16(uint32_t saddr, const void* gaddr) {
    asm volatile("cp.async.cg.shared.global [%0], [%1], 16;" :: "r"(saddr), "l"(gaddr));
}

__global__ __launch_bounds__(NTHREADS) void segnet_flowreg_warp_kernel(
    const float* __restrict__ cost,
    const float* __restrict__ feat,
    float* __restrict__ out)
{
    __shared__ float buf[2][UV][TILE];          // double-buffered cost tile
    __shared__ float s_max[BY][TILE];
    __shared__ int   s_am [BY][TILE];
    __shared__ float s_part[6][BY][TILE];

    const int tx  = threadIdx.x;                // pixel within tile
    const int ty  = threadIdx.y;                // uv chunk
    const int tid = tx + TILE * ty;

    const int tile0 = blockIdx.x * G;
    const uint32_t sb0 = (uint32_t)__cvta_generic_to_shared(&buf[0][0][0]);
    const uint32_t sb1 = (uint32_t)__cvta_generic_to_shared(&buf[1][0][0]);

    float* flow_o = out;
    float* ent_o  = out + (size_t)BATCH * 2 * HW;
    float* warp_o = out + (size_t)BATCH * 4 * HW;

    // ---- prologue: prefetch tile 0 into buf 0 ----
    {
        const int b   = tile0 / (HW / TILE);
        const int hw0 = (tile0 % (HW / TILE)) * TILE;
        const float* gbase = cost + (size_t)b * UV * HW + hw0;
        for (int j = tid; j < NCHUNK16; j += NTHREADS)
            cp16(sb0 + j * 16, gbase + (size_t)(j >> 4) * HW + (j & 15) * 4);
        asm volatile("cp.async.commit_group;");
    }

    for (int t = 0; t < G; t++) {
        const int tile = tile0 + t;
        const uint32_t sbuf = (t & 1) ? sb1 : sb0;
        const float (*cb)[TILE] = buf[t & 1];

        // prefetch next tile into the other buffer
        if (t + 1 < G) {
            const int tn  = tile + 1;
            const int b   = tn / (HW / TILE);
            const int hw0 = (tn % (HW / TILE)) * TILE;
            const float* gbase = cost + (size_t)b * UV * HW + hw0;
            const uint32_t snext = ((t + 1) & 1) ? sb1 : sb0;
            for (int j = tid; j < NCHUNK16; j += NTHREADS)
                cp16(snext + j * 16, gbase + (size_t)(j >> 4) * HW + (j & 15) * 4);
            asm volatile("cp.async.commit_group;");
            asm volatile("cp.async.wait_group 1;");   // tile t arrived
        } else {
            asm volatile("cp.async.wait_group 0;");
        }
        __syncthreads();                              // tile t visible to all
        (void)sbuf;

        const int b  = tile / (HW / TILE);
        const int hw = (tile % (HW / TILE)) * TILE + tx;
        const int h  = hw / W;
        const int w  = hw - h * W;

        // ---- pass 1: per-chunk max/argmax from smem ----
        float m  = -INFINITY;
        int   am = ty * CHUNK;
#pragma unroll
        for (int j = 0; j < CHUNK; j++) {
            float v = cb[ty * CHUNK + j][tx];
            if (v > m) { m = v; am = ty * CHUNK + j; }   // strict > : first occurrence
        }
        s_max[ty][tx] = m;
        s_am [ty][tx] = am;
        __syncthreads();

        float gm  = s_max[0][tx];
        int   gam = s_am [0][tx];
#pragma unroll
        for (int q = 1; q < BY; q++) {
            float v = s_max[q][tx];
            if (v > gm) { gm = v; gam = s_am[q][tx]; }
        }
        const int u0 = gam / 9;
        const int v0 = gam - 9 * u0;

        // ---- pass 2: exp sums (window max == global max; argmax in-window) ----
        float Sg = 0.f, Sg1 = 0.f, Sw = 0.f, Sw1 = 0.f, Sx = 0.f, Sy = 0.f;
#pragma unroll
        for (int ul = 0; ul < 3; ul++) {
            const int u = ty * 3 + ul;
            const bool uin = (u - u0 <= 3) && (u0 - u <= 3);
#pragma unroll
            for (int v = 0; v < 9; v++) {
                float d = cb[u * 9 + v][tx] - gm;
                float e = __expf(d);
                Sg  += e;
                Sg1 += e * d;
                bool inw = uin && (v - v0 <= 3) && (v0 - v <= 3);
                if (inw) {
                    Sw  += e;
                    Sw1 += e * d;
                    Sx  += e * (float)(u - 4);
                    Sy  += e * (float)(v - 4);
                }
            }
        }
        s_part[0][ty][tx] = Sg;  s_part[1][ty][tx] = Sg1;
        s_part[2][ty][tx] = Sw;  s_part[3][ty][tx] = Sw1;
        s_part[4][ty][tx] = Sx;  s_part[5][ty][tx] = Sy;
        __syncthreads();

        Sg = 0.f; Sg1 = 0.f; Sw = 0.f; Sw1 = 0.f; Sx = 0.f; Sy = 0.f;
#pragma unroll
        for (int q = 0; q < BY; q++) {
            Sg  += s_part[0][q][tx];  Sg1 += s_part[1][q][tx];
            Sw  += s_part[2][q][tx];  Sw1 += s_part[3][q][tx];
            Sx  += s_part[4][q][tx];  Sy  += s_part[5][q][tx];
        }
        const float invSw = 1.0f / Sw;
        const float fx = Sx * invSw;
        const float fy = Sy * invSw;

        if (ty == 0) {
            const float lent = (__logf(Sw) - Sw1 * invSw) * INV_LN49;
            const float gent = (__logf(Sg) - Sg1 / Sg)    * INV_LN81;
            flow_o[((size_t)b * 2 + 0) * HW + hw] = fx;
            flow_o[((size_t)b * 2 + 1) * HW + hw] = fy;
            ent_o [((size_t)b * 2 + 0) * HW + hw] = lent;
            ent_o [((size_t)b * 2 + 1) * HW + hw] = gent;
        }

        // ---- bilinear backward warp (align_corners=True, zero pad) ----
        const float px = (float)w + fx;
        const float py = (float)h + fy;
        const float x0f = floorf(px), y0f = floorf(py);
        const float wx = px - x0f,   wy = py - y0f;
        const int x0 = (int)x0f, y0 = (int)y0f;
        const int x1 = x0 + 1,   y1 = y0 + 1;
        const bool vx0 = (x0 >= 0) & (x0 < W);
        const bool vx1 = (x1 >= 0) & (x1 < W);
        const bool vy0 = (y0 >= 0) & (y0 < H);
        const bool vy1 = (y1 >= 0) & (y1 < H);

        float w00 = (1.f - wx) * (1.f - wy) * ((vx0 & vy0) ? 1.f : 0.f);
        float w01 = wx         * (1.f - wy) * ((vx1 & vy0) ? 1.f : 0.f);
        float w10 = (1.f - wx) * wy         * ((vx0 & vy1) ? 1.f : 0.f);
        float w11 = wx         * wy         * ((vx1 & vy1) ? 1.f : 0.f);

        const float nx = 2.f * px / (float)(W - 1) - 1.f;
        const float ny = 2.f * py / (float)(H - 1) - 1.f;
        const float msk = (fabsf(nx) < 1.f && fabsf(ny) < 1.f) ? 1.f : 0.f;
        w00 *= msk; w01 *= msk; w10 *= msk; w11 *= msk;

        const int x0c = min(max(x0, 0), W - 1), x1c = min(max(x1, 0), W - 1);
        const int y0c = min(max(y0, 0), H - 1), y1c = min(max(y1, 0), H - 1);
        const int o00 = y0c * W + x0c, o01 = y0c * W + x1c;
        const int o10 = y1c * W + x0c, o11 = y1c * W + x1c;

        const float* fb = feat + (size_t)b * NCH * HW;
#pragma unroll
        for (int ch = ty; ch < NCH; ch += BY) {
            const float* f = fb + ch * HW;
            float val = w00 * __ldg(f + o00) + w01 * __ldg(f + o01)
                      + w10 * __ldg(f + o10) + w11 * __ldg(f + o11);
            warp_o[((size_t)b * NCH + ch) * HW + hw] = val;
        }
        __syncthreads();   // protect buf[t&1] before prefetch of tile t+2
    }
}

extern "C" void kernel_launch(void* const* d_in, const int* in_sizes, int n_in,
                              void* d_out, int out_size) {
    const float* cost = (const float*)d_in[0];
    const float* feat = (const float*)d_in[1];
    float* out = (float*)d_out;

    dim3 block(TILE, BY);          // 192 threads
    int blocks = NTILES / G;       // 1536
    segnet_flowreg_warp_kernel<<<blocks, block>>>(cost, feat, out);
}